// round 1
// baseline (speedup 1.0000x reference)
#include <cuda_runtime.h>

#define NN     50000
#define CCH    128          // C == H == 128
#define SS     2048
#define KK     64
#define HH     128
#define EE     524288
#define LL     5
#define MROWS  (SS*KK)      // 131072

// ---------------- scratch (device globals; no allocations) ----------------
__device__ float g_M[CCH*HH];       // node_proj_w @ Wa (folded init weight)
__device__ float g_vlogp[HH];       // logp_proj_w @ Wb
__device__ float g_bias0[HH];       // folded init bias
__device__ float g_root[2*HH];      // root_emb @ Wc (both rows)
__device__ float g_z[MROWS*HH];
__device__ float g_t[MROWS*HH];
__device__ float g_u[MROWS*HH];
__device__ float g_xagg[NN*HH];
__device__ float g_inv[NN];
__device__ int   g_cnt[NN];
__device__ float g_stats[2*HH];

// ---------------- weight folding ----------------
__global__ void fold_M_kernel(const float* __restrict__ npw, const float* __restrict__ ipw) {
    int i = blockIdx.x;       // input channel
    int j = threadIdx.x;      // output channel
    float s = 0.f;
    for (int k = 0; k < HH; k++) s += npw[i*HH + k] * ipw[k*HH + j];
    g_M[i*HH + j] = s;
}

__global__ void fold_vec_kernel(const float* __restrict__ lpw, const float* __restrict__ npb,
                                const float* __restrict__ lpb, const float* __restrict__ remb,
                                const float* __restrict__ ipw, const float* __restrict__ ipb) {
    int j = threadIdx.x;
    float v = 0.f, b = ipb[j], r0 = 0.f, r1 = 0.f;
    for (int k = 0; k < HH; k++) {
        float wa = ipw[k*HH + j];
        float wb = ipw[(HH + k)*HH + j];
        float wc = ipw[(2*HH + k)*HH + j];
        v  += lpw[k] * wb;
        b  += npb[k] * wa + lpb[k] * wb;
        r0 += remb[k] * wc;
        r1 += remb[HH + k] * wc;
    }
    g_vlogp[j] = v;
    g_bias0[j] = b;
    g_root[j] = r0;
    g_root[HH + j] = r1;
}

// ---------------- counts for scatter-mean ----------------
__global__ void zero_cnt_kernel() {
    int i = blockIdx.x*blockDim.x + threadIdx.x;
    if (i < NN) g_cnt[i] = 0;
}
__global__ void count_kernel(const int* __restrict__ nodes) {
    int i = blockIdx.x*blockDim.x + threadIdx.x;
    if (i < MROWS) atomicAdd(&g_cnt[nodes[i]], 1);
}
__global__ void inv_kernel() {
    int i = blockIdx.x*blockDim.x + threadIdx.x;
    if (i < NN) g_inv[i] = 1.f / (float)max(g_cnt[i], 1);
}

// ---------------- tiled SGEMM: [MROWS,K] @ [K,128] ----------------
// MODE 0: C = A@B + bias
// MODE 1: C = relu(A@B + bias)
// MODE 2: init: A = x gathered via aidx; B = g_M; epilogue adds lp*v + root + g_bias0
// MODE 3: mp2: K=256; kt<8 from A (z), kt>=8 gathered from A2 (xagg) * inv[row]; relu(+bias)
template<int MODE>
__global__ void __launch_bounds__(256)
sgemm_kernel(const float* __restrict__ A, const float* __restrict__ B,
             float* __restrict__ Cout, const float* __restrict__ bias,
             const int* __restrict__ aidx, const float* __restrict__ A2,
             const float* __restrict__ inv, const float* __restrict__ logp,
             const int* __restrict__ rootl)
{
    __shared__ float As[16][128];   // [k][m]
    __shared__ float Bs[16][128];   // [k][n]
    const int tid = threadIdx.x;
    const int tx = tid & 15, ty = tid >> 4;
    const int brow = blockIdx.x * 128;

    const float* Bp = (MODE == 2) ? (const float*)g_M : B;
    const float* bp = (MODE == 2) ? (const float*)g_bias0 : bias;

    float acc[8][8];
    #pragma unroll
    for (int i = 0; i < 8; i++)
        #pragma unroll
        for (int j = 0; j < 8; j++) acc[i][j] = 0.f;

    const int KT = (MODE == 3) ? 16 : 8;
    for (int kt = 0; kt < KT; kt++) {
        // ---- A tile: 128 rows x 16 k ----
        #pragma unroll
        for (int it = 0; it < 2; it++) {
            int item = tid + it*256;            // 0..511
            int r = item >> 2, kq = item & 3;
            int gr = brow + r;
            float4 v;
            if (MODE == 2) {
                int ar = aidx[gr];
                v = *(const float4*)(A + (size_t)ar*HH + kt*16 + kq*4);
            } else if (MODE == 3) {
                if (kt < 8) {
                    v = *(const float4*)(A + (size_t)gr*HH + kt*16 + kq*4);
                } else {
                    int ar = aidx[gr];
                    float sc = inv[ar];
                    v = *(const float4*)(A2 + (size_t)ar*HH + (kt-8)*16 + kq*4);
                    v.x *= sc; v.y *= sc; v.z *= sc; v.w *= sc;
                }
            } else {
                v = *(const float4*)(A + (size_t)gr*HH + kt*16 + kq*4);
            }
            As[kq*4+0][r] = v.x; As[kq*4+1][r] = v.y;
            As[kq*4+2][r] = v.z; As[kq*4+3][r] = v.w;
        }
        // ---- B tile: 16 k x 128 n ----
        #pragma unroll
        for (int it = 0; it < 2; it++) {
            int item = tid + it*256;
            int r = item >> 5, cq = item & 31;
            *(float4*)&Bs[r][cq*4] = *(const float4*)(Bp + (size_t)(kt*16 + r)*HH + cq*4);
        }
        __syncthreads();
        #pragma unroll
        for (int kk = 0; kk < 16; kk++) {
            float af[8], bf[8];
            *(float4*)&af[0] = *(float4*)&As[kk][ty*8];
            *(float4*)&af[4] = *(float4*)&As[kk][ty*8 + 4];
            *(float4*)&bf[0] = *(float4*)&Bs[kk][tx*8];
            *(float4*)&bf[4] = *(float4*)&Bs[kk][tx*8 + 4];
            #pragma unroll
            for (int i = 0; i < 8; i++)
                #pragma unroll
                for (int j = 0; j < 8; j++)
                    acc[i][j] += af[i] * bf[j];
        }
        __syncthreads();
    }

    // ---- epilogue ----
    #pragma unroll
    for (int i = 0; i < 8; i++) {
        int gr = brow + ty*8 + i;
        float lp = 0.f; int isr = 0;
        if (MODE == 2) {
            int sub = gr >> 6;
            lp = logp[sub];
            isr = ((gr & 63) == rootl[sub]) ? 1 : 0;
        }
        #pragma unroll
        for (int jj = 0; jj < 2; jj++) {
            float4 o;
            float* po = (float*)&o;
            #pragma unroll
            for (int j2 = 0; j2 < 4; j2++) {
                int j = jj*4 + j2;
                int gc = tx*8 + j;
                float val = acc[i][j] + bp[gc];
                if (MODE == 2) val += lp * g_vlogp[gc] + g_root[isr*HH + gc];
                if (MODE == 1 || MODE == 3) val = fmaxf(val, 0.f);
                po[j2] = val;
            }
            *(float4*)(Cout + (size_t)gr*HH + tx*8 + jj*4) = o;
        }
    }
}

// ---------------- per-subgraph edge aggregation (GIN input) ----------------
// z[i] = (1+eps)*h[i] + sum_{(s,d) in edges, d==i} h[s]
__global__ void agg_kernel(const float* __restrict__ h, float* __restrict__ zout,
                           const int* __restrict__ esrc, const int* __restrict__ edst,
                           const int* __restrict__ eptr, const float* __restrict__ geps,
                           int l)
{
    __shared__ float acc[KK][HH];   // 32 KB
    __shared__ int se[256], de[256];
    const int s = blockIdx.x;
    const int tid = threadIdx.x;    // 128, one per column
    const float eps1 = 1.f + geps[l];
    const size_t base = (size_t)s * KK;

    #pragma unroll 4
    for (int r = 0; r < KK; r++)
        acc[r][tid] = eps1 * h[(base + r)*HH + tid];
    __syncthreads();

    const int e0 = eptr[s], e1 = eptr[s+1];
    for (int eb = e0; eb < e1; eb += 256) {
        int ne = min(256, e1 - eb);
        for (int i = tid; i < ne; i += 128) {
            se[i] = esrc[eb + i];
            de[i] = edst[eb + i];
        }
        __syncthreads();
        for (int i = 0; i < ne; i++)
            acc[de[i]][tid] += __ldg(&h[(base + se[i])*HH + tid]);
        __syncthreads();
    }

    #pragma unroll 4
    for (int r = 0; r < KK; r++)
        zout[(base + r)*HH + tid] = acc[r][tid];
}

// ---------------- scatter-mean pieces ----------------
__global__ void zero_xagg_kernel() {
    int i = blockIdx.x*blockDim.x + threadIdx.x;   // covers NN*HH exactly
    g_xagg[i] = 0.f;
    if (i < 2*HH) g_stats[i] = 0.f;
}
__global__ void scatter_kernel(const float* __restrict__ z, const int* __restrict__ nodes) {
    int idx = blockIdx.x*blockDim.x + threadIdx.x;  // covers MROWS*HH exactly
    int row = idx >> 7, c = idx & 127;
    atomicAdd(&g_xagg[(size_t)nodes[row]*HH + c], z[idx]);
}

// ---------------- batchnorm ----------------
__global__ void bn_reduce_kernel(const float* __restrict__ u) {
    int c = threadIdx.x;   // 128
    float s = 0.f, ss = 0.f;
    for (int r = blockIdx.x; r < MROWS; r += gridDim.x) {
        float v = u[(size_t)r*HH + c];
        s += v; ss += v*v;
    }
    atomicAdd(&g_stats[c], s);
    atomicAdd(&g_stats[HH + c], ss);
}
__global__ void bn_apply_kernel(const float* __restrict__ u, float* __restrict__ h,
                                const float* __restrict__ gamma, const float* __restrict__ beta) {
    int idx = blockIdx.x*blockDim.x + threadIdx.x;  // covers MROWS*HH exactly
    int c = idx & 127;
    const float invM = 1.f / (float)MROWS;
    float mu  = g_stats[c] * invM;
    float var = g_stats[HH + c] * invM - mu*mu;
    float g = gamma[c] * rsqrtf(var + 1e-5f);
    h[idx] = (u[idx] - mu) * g + beta[c] + h[idx];
}

// ---------------- launch ----------------
extern "C" void kernel_launch(void* const* d_in, const int* in_sizes, int n_in,
                              void* d_out, int out_size) {
    const float* x    = (const float*)d_in[0];
    const float* logp = (const float*)d_in[1];
    const float* npw  = (const float*)d_in[2];
    const float* npb  = (const float*)d_in[3];
    const float* lpw  = (const float*)d_in[4];
    const float* lpb  = (const float*)d_in[5];
    const float* remb = (const float*)d_in[6];
    const float* ipw  = (const float*)d_in[7];
    const float* ipb  = (const float*)d_in[8];
    const float* geps = (const float*)d_in[9];
    const float* w1   = (const float*)d_in[10];
    const float* b1   = (const float*)d_in[11];
    const float* w2   = (const float*)d_in[12];
    const float* b2   = (const float*)d_in[13];
    const float* mp2w = (const float*)d_in[14];
    const float* mp2b = (const float*)d_in[15];
    const float* bng  = (const float*)d_in[16];
    const float* bnb  = (const float*)d_in[17];
    const int* nodes  = (const int*)d_in[18];
    const int* rootl  = (const int*)d_in[19];
    const int* eidx   = (const int*)d_in[20];
    const int* eptr   = (const int*)d_in[21];
    float* hout = (float*)d_out;

    float *p_z, *p_t, *p_u, *p_xagg, *p_inv;
    cudaGetSymbolAddress((void**)&p_z, g_z);
    cudaGetSymbolAddress((void**)&p_t, g_t);
    cudaGetSymbolAddress((void**)&p_u, g_u);
    cudaGetSymbolAddress((void**)&p_xagg, g_xagg);
    cudaGetSymbolAddress((void**)&p_inv, g_inv);

    const int* esrc = eidx;
    const int* edst = eidx + EE;

    // ---- prologue: fold weights, node counts ----
    fold_M_kernel<<<128, 128>>>(npw, ipw);
    fold_vec_kernel<<<1, 128>>>(lpw, npb, lpb, remb, ipw, ipb);
    zero_cnt_kernel<<<(NN + 255)/256, 256>>>();
    count_kernel<<<MROWS/256, 256>>>(nodes);
    inv_kernel<<<(NN + 255)/256, 256>>>();

    // ---- init: h = gather(x)@M + lp*v + root + bias ----
    sgemm_kernel<2><<<MROWS/128, 256>>>(x, nullptr, hout, nullptr,
                                        nodes, nullptr, nullptr, logp, rootl);

    // ---- layers ----
    for (int l = 0; l < LL; l++) {
        agg_kernel<<<SS, 128>>>(hout, p_z, esrc, edst, eptr, geps, l);

        sgemm_kernel<1><<<MROWS/128, 256>>>(p_z, w1 + (size_t)l*HH*HH, p_t,
                                            b1 + l*HH, nullptr, nullptr, nullptr,
                                            nullptr, nullptr);
        sgemm_kernel<0><<<MROWS/128, 256>>>(p_t, w2 + (size_t)l*HH*HH, p_z,
                                            b2 + l*HH, nullptr, nullptr, nullptr,
                                            nullptr, nullptr);

        zero_xagg_kernel<<<(NN*HH)/256, 256>>>();
        scatter_kernel<<<(MROWS*HH)/256, 256>>>(p_z, nodes);

        sgemm_kernel<3><<<MROWS/128, 256>>>(p_z, mp2w + (size_t)l*2*HH*HH, p_u,
                                            mp2b + l*HH, nodes, p_xagg, p_inv,
                                            nullptr, nullptr);

        bn_reduce_kernel<<<512, 128>>>(p_u);
        bn_apply_kernel<<<(MROWS*HH)/256, 256>>>(p_u, hout, bng + l*HH, bnb + l*HH);
    }
}

// round 3
// speedup vs baseline: 1.3440x; 1.3440x over previous
#include <cuda_runtime.h>
#include <cuda_bf16.h>

#define NN     50000
#define SS     2048
#define KK     64
#define HH     128
#define EE     524288
#define LL     5
#define MROWS  (SS*KK)      // 131072

// ---------------- scratch (device globals; no allocations) ----------------
__device__ unsigned g_Mp1[HH*HH];        // folded init weight, packed (bh,bh)
__device__ unsigned g_Mp2[HH*HH];        // packed (bl, 0)
__device__ float    g_vlogp[HH];
__device__ float    g_bias0[HH];
__device__ float    g_root[2*HH];
__device__ unsigned g_w1p1[LL*HH*HH], g_w1p2[LL*HH*HH];
__device__ unsigned g_w2p1[LL*HH*HH], g_w2p2[LL*HH*HH];
__device__ unsigned g_mp2p1[LL*HH*2*HH], g_mp2p2[LL*HH*2*HH];
__device__ float g_z[MROWS*HH];
__device__ float g_t[MROWS*HH];
__device__ float g_u[MROWS*HH];
__device__ float g_xagg[NN*HH];
__device__ float g_inv[NN];
__device__ int   g_cnt[NN];
__device__ float g_stats[2*HH];

// ---- split-bf16 packing helpers ----
__device__ __forceinline__ unsigned pack_a(float v) {
    __nv_bfloat16 hi = __float2bfloat16_rn(v);
    __nv_bfloat16 lo = __float2bfloat16_rn(v - __bfloat162float(hi));
    return (unsigned)__bfloat16_as_ushort(hi)
         | ((unsigned)__bfloat16_as_ushort(lo) << 16);
}
__device__ __forceinline__ void pack_w(float w, unsigned& p1, unsigned& p2) {
    __nv_bfloat16 hi = __float2bfloat16_rn(w);
    __nv_bfloat16 lo = __float2bfloat16_rn(w - __bfloat162float(hi));
    unsigned h = __bfloat16_as_ushort(hi);
    unsigned l = __bfloat16_as_ushort(lo);
    p1 = h | (h << 16);   // pairs (ah, al): ah*bh + al*bh
    p2 = l;               // pairs (ah, al): ah*bl + al*0
}

// ---------------- weight folding / packing ----------------
__global__ void fold_M_kernel(const float* __restrict__ npw, const float* __restrict__ ipw) {
    int i = blockIdx.x;       // input channel (k)
    int j = threadIdx.x;      // output channel (n)
    float s = 0.f;
    for (int k = 0; k < HH; k++) s += npw[i*HH + k] * ipw[k*HH + j];
    unsigned p1, p2; pack_w(s, p1, p2);
    g_Mp1[j*HH + i] = p1;
    g_Mp2[j*HH + i] = p2;
}

__global__ void fold_vec_kernel(const float* __restrict__ lpw, const float* __restrict__ npb,
                                const float* __restrict__ lpb, const float* __restrict__ remb,
                                const float* __restrict__ ipw, const float* __restrict__ ipb) {
    int j = threadIdx.x;
    float v = 0.f, b = ipb[j], r0 = 0.f, r1 = 0.f;
    for (int k = 0; k < HH; k++) {
        float wa = ipw[k*HH + j];
        float wb = ipw[(HH + k)*HH + j];
        float wc = ipw[(2*HH + k)*HH + j];
        v  += lpw[k] * wb;
        b  += npb[k] * wa + lpb[k] * wb;
        r0 += remb[k] * wc;
        r1 += remb[HH + k] * wc;
    }
    g_vlogp[j] = v;
    g_bias0[j] = b;
    g_root[j] = r0;
    g_root[HH + j] = r1;
}

// W: [L][Kdim][128] row-major -> packed [L][128][Kdim]
__global__ void transpose_pack_kernel(const float* __restrict__ W,
                                      unsigned* __restrict__ P1, unsigned* __restrict__ P2,
                                      int Kdim) {
    int idx = blockIdx.x*blockDim.x + threadIdx.x;   // covers Kdim*128
    int l = blockIdx.y;
    int k = idx / HH, n = idx % HH;
    float w = W[(size_t)l*Kdim*HH + idx];
    unsigned p1, p2; pack_w(w, p1, p2);
    P1[(size_t)l*HH*Kdim + (size_t)n*Kdim + k] = p1;
    P2[(size_t)l*HH*Kdim + (size_t)n*Kdim + k] = p2;
}

// ---------------- counts for scatter-mean ----------------
__global__ void zero_cnt_kernel() {
    int i = blockIdx.x*blockDim.x + threadIdx.x;
    if (i < NN) g_cnt[i] = 0;
}
__global__ void count_kernel(const int* __restrict__ nodes) {
    int i = blockIdx.x*blockDim.x + threadIdx.x;
    if (i < MROWS) atomicAdd(&g_cnt[nodes[i]], 1);
}
__global__ void inv_kernel() {
    int i = blockIdx.x*blockDim.x + threadIdx.x;
    if (i < NN) g_inv[i] = 1.f / (float)max(g_cnt[i], 1);
}

// ---------------- split-bf16 tensor GEMM: [MROWS,K] @ W^T -> [MROWS,128] ----------------
// MODE 0: C = A@W + bias
// MODE 1: C = relu(A@W + bias)
// MODE 2: init: A = x gathered via aidx; W = folded M; epilogue adds lp*v + root + bias0
// MODE 3: mp2: K=256; kt<4 from A (z), kt>=4 gathered from A2 (xagg) * inv; relu(+bias)

#define LDSM4(R0,R1,R2,R3,ADDR) \
    asm volatile("ldmatrix.sync.aligned.m8n8.x4.shared.b16 {%0,%1,%2,%3}, [%4];" \
        : "=r"(R0),"=r"(R1),"=r"(R2),"=r"(R3) : "r"(ADDR))

#define MMA_BF16(C, A0,A1,A2,A3, B0,B1) \
    asm volatile("mma.sync.aligned.m16n8k16.row.col.f32.bf16.bf16.f32 " \
        "{%0,%1,%2,%3},{%4,%5,%6,%7},{%8,%9},{%0,%1,%2,%3};" \
        : "+f"(C[0]),"+f"(C[1]),"+f"(C[2]),"+f"(C[3]) \
        : "r"(A0),"r"(A1),"r"(A2),"r"(A3),"r"(B0),"r"(B1))

#define SROW 36                       // smem row stride in uint32 (32 data + 4 pad)
#define TILE_U32 (128*SROW)           // one tile in uint32
#define SMEM_BYTES (3*TILE_U32*4)     // As + Bs1 + Bs2 = 55296 B

template<int MODE>
__global__ void __launch_bounds__(256)
mma_gemm(const float* __restrict__ A,
         const unsigned* __restrict__ Wp1, const unsigned* __restrict__ Wp2,
         float* __restrict__ Cout, const float* __restrict__ bias,
         const int* __restrict__ aidx, const float* __restrict__ A2,
         const float* __restrict__ inv, const float* __restrict__ logp,
         const int* __restrict__ rootl)
{
    extern __shared__ __align__(16) unsigned sm[];
    unsigned* As  = sm;
    unsigned* Bs1 = sm + TILE_U32;
    unsigned* Bs2 = sm + 2*TILE_U32;

    const int tid = threadIdx.x;
    const int lane = tid & 31, warp = tid >> 5;
    const int wm = warp & 3, wn = warp >> 2;     // warp tile: 32(m) x 64(n)
    const int brow = blockIdx.x * 128;
    const int KROW = (MODE == 3) ? 256 : 128;
    const int KT   = (MODE == 3) ? 8 : 4;

    const float* bp = (MODE == 2) ? (const float*)g_bias0 : bias;

    float c[2][8][4];
    #pragma unroll
    for (int i = 0; i < 2; i++)
        #pragma unroll
        for (int j = 0; j < 8; j++)
            #pragma unroll
            for (int q = 0; q < 4; q++) c[i][j][q] = 0.f;

    // ldmatrix byte addresses
    unsigned aB = (unsigned)__cvta_generic_to_shared(As);
    unsigned bB = (unsigned)__cvta_generic_to_shared(Bs1);
    const unsigned SRB = SROW*4;          // row stride bytes (144)
    const unsigned B2OFF = TILE_U32*4;    // Bs2 - Bs1 bytes

    unsigned a_addr[2], b_addr[4];
    #pragma unroll
    for (int mf = 0; mf < 2; mf++) {
        int row = wm*32 + mf*16 + (lane & 15);
        a_addr[mf] = aB + row*SRB + (lane>>4)*16;
    }
    #pragma unroll
    for (int g = 0; g < 4; g++) {
        int row = wn*64 + g*16 + ((lane>>3)&1)*8 + (lane&7);
        b_addr[g] = bB + row*SRB + (lane>>4)*16;
    }

    for (int kt = 0; kt < KT; kt++) {
        // ---- A tile: 128 rows x 32 k, split-bf16 packed ----
        #pragma unroll
        for (int it = 0; it < 4; it++) {
            int item = tid + it*256;
            int r = item >> 3, q = item & 7;
            int gr = brow + r;
            float4 v;
            if (MODE == 2) {
                int ar = aidx[gr];
                v = *(const float4*)(A + (size_t)ar*HH + kt*32 + q*4);
            } else if (MODE == 3) {
                if (kt < 4) {
                    v = *(const float4*)(A + (size_t)gr*HH + kt*32 + q*4);
                } else {
                    int ar = aidx[gr];
                    float sc = inv[ar];
                    v = *(const float4*)(A2 + (size_t)ar*HH + (kt-4)*32 + q*4);
                    v.x *= sc; v.y *= sc; v.z *= sc; v.w *= sc;
                }
            } else {
                v = *(const float4*)(A + (size_t)gr*HH + kt*32 + q*4);
            }
            uint4 t;
            t.x = pack_a(v.x); t.y = pack_a(v.y); t.z = pack_a(v.z); t.w = pack_a(v.w);
            *(uint4*)&As[r*SROW + q*4] = t;
        }
        // ---- B tiles: both packed weight variants: 128 n x 32 k ----
        #pragma unroll
        for (int it = 0; it < 4; it++) {
            int item = tid + it*256;
            int r = item >> 3, q = item & 7;
            *(uint4*)&Bs1[r*SROW + q*4] = *(const uint4*)(Wp1 + (size_t)r*KROW + kt*32 + q*4);
            *(uint4*)&Bs2[r*SROW + q*4] = *(const uint4*)(Wp2 + (size_t)r*KROW + kt*32 + q*4);
        }
        __syncthreads();

        #pragma unroll
        for (int ks = 0; ks < 4; ks++) {      // each ks = 8 real k = one k16 mma step
            unsigned a0[4], a1[4];
            LDSM4(a0[0],a0[1],a0[2],a0[3], a_addr[0] + ks*32);
            LDSM4(a1[0],a1[1],a1[2],a1[3], a_addr[1] + ks*32);
            #pragma unroll
            for (int g = 0; g < 4; g++) {
                unsigned b[4];
                LDSM4(b[0],b[1],b[2],b[3], b_addr[g] + ks*32);
                MMA_BF16(c[0][2*g+0], a0[0],a0[1],a0[2],a0[3], b[0],b[2]);
                MMA_BF16(c[0][2*g+1], a0[0],a0[1],a0[2],a0[3], b[1],b[3]);
                MMA_BF16(c[1][2*g+0], a1[0],a1[1],a1[2],a1[3], b[0],b[2]);
                MMA_BF16(c[1][2*g+1], a1[0],a1[1],a1[2],a1[3], b[1],b[3]);
                LDSM4(b[0],b[1],b[2],b[3], b_addr[g] + B2OFF + ks*32);
                MMA_BF16(c[0][2*g+0], a0[0],a0[1],a0[2],a0[3], b[0],b[2]);
                MMA_BF16(c[0][2*g+1], a0[0],a0[1],a0[2],a0[3], b[1],b[3]);
                MMA_BF16(c[1][2*g+0], a1[0],a1[1],a1[2],a1[3], b[0],b[2]);
                MMA_BF16(c[1][2*g+1], a1[0],a1[1],a1[2],a1[3], b[1],b[3]);
            }
        }
        __syncthreads();
    }

    // ---- epilogue ----
    const int gid = lane >> 2, tig = lane & 3;
    #pragma unroll
    for (int mf = 0; mf < 2; mf++) {
        #pragma unroll
        for (int half = 0; half < 2; half++) {
            int m = wm*32 + mf*16 + half*8 + gid;
            int gr = brow + m;
            float lp = 0.f; int isr = 0;
            if (MODE == 2) {
                int sub = gr >> 6;
                lp = logp[sub];
                isr = ((gr & 63) == rootl[sub]) ? 1 : 0;
            }
            #pragma unroll
            for (int nf = 0; nf < 8; nf++) {
                int n0 = wn*64 + nf*8 + tig*2;
                float v0 = c[mf][nf][half*2+0] + bp[n0];
                float v1 = c[mf][nf][half*2+1] + bp[n0+1];
                if (MODE == 2) {
                    v0 += lp * g_vlogp[n0]   + g_root[isr*HH + n0];
                    v1 += lp * g_vlogp[n0+1] + g_root[isr*HH + n0+1];
                }
                if (MODE == 1 || MODE == 3) { v0 = fmaxf(v0, 0.f); v1 = fmaxf(v1, 0.f); }
                float2 o; o.x = v0; o.y = v1;
                *(float2*)(Cout + (size_t)gr*HH + n0) = o;
            }
        }
    }
}

// ---------------- per-subgraph edge aggregation (GIN input) ----------------
__global__ void agg_kernel(const float* __restrict__ h, float* __restrict__ zout,
                           const int* __restrict__ esrc, const int* __restrict__ edst,
                           const int* __restrict__ eptr, const float* __restrict__ geps,
                           int l)
{
    __shared__ float acc[KK][HH];
    __shared__ int se[256], de[256];
    const int s = blockIdx.x;
    const int tid = threadIdx.x;    // 128, one per column
    const float eps1 = 1.f + geps[l];
    const size_t base = (size_t)s * KK;

    #pragma unroll 4
    for (int r = 0; r < KK; r++)
        acc[r][tid] = eps1 * h[(base + r)*HH + tid];
    __syncthreads();

    const int e0 = eptr[s], e1 = eptr[s+1];
    for (int eb = e0; eb < e1; eb += 256) {
        int ne = min(256, e1 - eb);
        for (int i = tid; i < ne; i += 128) {
            se[i] = esrc[eb + i];
            de[i] = edst[eb + i];
        }
        __syncthreads();
        for (int i = 0; i < ne; i++)
            acc[de[i]][tid] += __ldg(&h[(base + se[i])*HH + tid]);
        __syncthreads();
    }

    #pragma unroll 4
    for (int r = 0; r < KK; r++)
        zout[(base + r)*HH + tid] = acc[r][tid];
}

// ---------------- scatter-mean pieces ----------------
__global__ void zero_xagg_kernel() {
    int i = blockIdx.x*blockDim.x + threadIdx.x;   // covers NN*HH exactly
    g_xagg[i] = 0.f;
    if (i < 2*HH) g_stats[i] = 0.f;
}
__global__ void scatter_kernel(const float* __restrict__ z, const int* __restrict__ nodes) {
    int idx = blockIdx.x*blockDim.x + threadIdx.x;  // covers MROWS*HH exactly
    int row = idx >> 7, c = idx & 127;
    atomicAdd(&g_xagg[(size_t)nodes[row]*HH + c], z[idx]);
}

// ---------------- batchnorm ----------------
__global__ void bn_reduce_kernel(const float* __restrict__ u) {
    int c = threadIdx.x;
    float s = 0.f, ss = 0.f;
    for (int r = blockIdx.x; r < MROWS; r += gridDim.x) {
        float v = u[(size_t)r*HH + c];
        s += v; ss += v*v;
    }
    atomicAdd(&g_stats[c], s);
    atomicAdd(&g_stats[HH + c], ss);
}
__global__ void bn_apply_kernel(const float* __restrict__ u, float* __restrict__ h,
                                const float* __restrict__ gamma, const float* __restrict__ beta) {
    int idx = blockIdx.x*blockDim.x + threadIdx.x;
    int c = idx & 127;
    const float invM = 1.f / (float)MROWS;
    float mu  = g_stats[c] * invM;
    float var = g_stats[HH + c] * invM - mu*mu;
    float g = gamma[c] * rsqrtf(var + 1e-5f);
    h[idx] = (u[idx] - mu) * g + beta[c] + h[idx];
}

// ---------------- launch ----------------
extern "C" void kernel_launch(void* const* d_in, const int* in_sizes, int n_in,
                              void* d_out, int out_size) {
    const float* x    = (const float*)d_in[0];
    const float* logp = (const float*)d_in[1];
    const float* npw  = (const float*)d_in[2];
    const float* npb  = (const float*)d_in[3];
    const float* lpw  = (const float*)d_in[4];
    const float* lpb  = (const float*)d_in[5];
    const float* remb = (const float*)d_in[6];
    const float* ipw  = (const float*)d_in[7];
    const float* ipb  = (const float*)d_in[8];
    const float* geps = (const float*)d_in[9];
    const float* w1   = (const float*)d_in[10];
    const float* b1   = (const float*)d_in[11];
    const float* w2   = (const float*)d_in[12];
    const float* b2   = (const float*)d_in[13];
    const float* mp2w = (const float*)d_in[14];
    const float* mp2b = (const float*)d_in[15];
    const float* bng  = (const float*)d_in[16];
    const float* bnb  = (const float*)d_in[17];
    const int* nodes  = (const int*)d_in[18];
    const int* rootl  = (const int*)d_in[19];
    const int* eidx   = (const int*)d_in[20];
    const int* eptr   = (const int*)d_in[21];
    float* hout = (float*)d_out;

    float *p_z, *p_t, *p_u, *p_xagg, *p_inv;
    unsigned *p_w1p1, *p_w1p2, *p_w2p1, *p_w2p2, *p_mp2p1, *p_mp2p2, *p_Mp1, *p_Mp2;
    cudaGetSymbolAddress((void**)&p_z, g_z);
    cudaGetSymbolAddress((void**)&p_t, g_t);
    cudaGetSymbolAddress((void**)&p_u, g_u);
    cudaGetSymbolAddress((void**)&p_xagg, g_xagg);
    cudaGetSymbolAddress((void**)&p_inv, g_inv);
    cudaGetSymbolAddress((void**)&p_w1p1, g_w1p1);
    cudaGetSymbolAddress((void**)&p_w1p2, g_w1p2);
    cudaGetSymbolAddress((void**)&p_w2p1, g_w2p1);
    cudaGetSymbolAddress((void**)&p_w2p2, g_w2p2);
    cudaGetSymbolAddress((void**)&p_mp2p1, g_mp2p1);
    cudaGetSymbolAddress((void**)&p_mp2p2, g_mp2p2);
    cudaGetSymbolAddress((void**)&p_Mp1, g_Mp1);
    cudaGetSymbolAddress((void**)&p_Mp2, g_Mp2);

    cudaFuncSetAttribute(mma_gemm<0>, cudaFuncAttributeMaxDynamicSharedMemorySize, SMEM_BYTES);
    cudaFuncSetAttribute(mma_gemm<1>, cudaFuncAttributeMaxDynamicSharedMemorySize, SMEM_BYTES);
    cudaFuncSetAttribute(mma_gemm<2>, cudaFuncAttributeMaxDynamicSharedMemorySize, SMEM_BYTES);
    cudaFuncSetAttribute(mma_gemm<3>, cudaFuncAttributeMaxDynamicSharedMemorySize, SMEM_BYTES);

    const int* esrc = eidx;
    const int* edst = eidx + EE;

    // ---- prologue: fold weights, pack to split-bf16, node counts ----
    fold_M_kernel<<<128, 128>>>(npw, ipw);
    fold_vec_kernel<<<1, 128>>>(lpw, npb, lpb, remb, ipw, ipb);
    transpose_pack_kernel<<<dim3(64, LL), 256>>>(w1, p_w1p1, p_w1p2, 128);
    transpose_pack_kernel<<<dim3(64, LL), 256>>>(w2, p_w2p1, p_w2p2, 128);
    transpose_pack_kernel<<<dim3(128, LL), 256>>>(mp2w, p_mp2p1, p_mp2p2, 256);
    zero_cnt_kernel<<<(NN + 255)/256, 256>>>();
    count_kernel<<<MROWS/256, 256>>>(nodes);
    inv_kernel<<<(NN + 255)/256, 256>>>();

    // ---- init: h = gather(x)@M + lp*v + root + bias ----
    mma_gemm<2><<<MROWS/128, 256, SMEM_BYTES>>>(x, p_Mp1, p_Mp2, hout, nullptr,
                                                nodes, nullptr, nullptr, logp, rootl);

    // ---- layers ----
    for (int l = 0; l < LL; l++) {
        agg_kernel<<<SS, 128>>>(hout, p_z, esrc, edst, eptr, geps, l);

        mma_gemm<1><<<MROWS/128, 256, SMEM_BYTES>>>(p_z, p_w1p1 + (size_t)l*HH*HH,
                                                    p_w1p2 + (size_t)l*HH*HH, p_t,
                                                    b1 + l*HH, nullptr, nullptr, nullptr,
                                                    nullptr, nullptr);
        mma_gemm<0><<<MROWS/128, 256, SMEM_BYTES>>>(p_t, p_w2p1 + (size_t)l*HH*HH,
                                                    p_w2p2 + (size_t)l*HH*HH, p_z,
                                                    b2 + l*HH, nullptr, nullptr, nullptr,
                                                    nullptr, nullptr);

        zero_xagg_kernel<<<(NN*HH)/256, 256>>>();
        scatter_kernel<<<(MROWS*HH)/256, 256>>>(p_z, nodes);

        mma_gemm<3><<<MROWS/128, 256, SMEM_BYTES>>>(p_z, p_mp2p1 + (size_t)l*HH*2*HH,
                                                    p_mp2p2 + (size_t)l*HH*2*HH, p_u,
                                                    mp2b + l*HH, nodes, p_xagg, p_inv,
                                                    nullptr, nullptr);

        bn_reduce_kernel<<<512, 128>>>(p_u);
        bn_apply_kernel<<<(MROWS*HH)/256, 256>>>(p_u, hout, bng + l*HH, bnb + l*HH);
    }
}